// round 4
// baseline (speedup 1.0000x reference)
#include <cuda_runtime.h>

#define NCOEF 1001            // degree 1000 -> 1001 coefficients
#define THREADS_PER_BLOCK 64
#define ELEMS_PER_THREAD 8    // four f32x2 Horner chains per thread

typedef unsigned long long u64;

__device__ __forceinline__ u64 pk2(float a, float b) {
    u64 r;
    asm("mov.b64 %0, {%1, %2};" : "=l"(r) : "f"(a), "f"(b));
    return r;
}
__device__ __forceinline__ u64 ffma2(u64 a, u64 b, u64 c) {
    u64 d;
    asm("fma.rn.f32x2 %0, %1, %2, %3;" : "=l"(d) : "l"(a), "l"(b), "l"(c));
    return d;
}

__global__ __launch_bounds__(THREADS_PER_BLOCK)
void poly_horner_kernel(const float* __restrict__ x,
                        const float* __restrict__ w,
                        float* __restrict__ out) {
    // w duplicated into (w_i, w_i) pairs; hot loop reads ulonglong2
    // (ld.shared.v2.u64 broadcast) -> two ready FFMA2 c-operands per 16B,
    // each now amortized over FOUR Horner chains (8 FFMA2 per coeff pair).
    __shared__ __align__(16) float2 w2s[NCOEF + 1];

    const int t = blockIdx.x * THREADS_PER_BLOCK + threadIdx.x;
    const float4* x4 = reinterpret_cast<const float4*>(x) + 2 * t;
    const float4 xa = x4[0];               // elements 8t .. 8t+3
    const float4 xb = x4[1];               // elements 8t+4 .. 8t+7

    for (int i = threadIdx.x; i < NCOEF; i += THREADS_PER_BLOCK) {
        float v = w[i];
        w2s[i] = make_float2(v, v);
    }
    __syncthreads();

    const u64 x01 = pk2(xa.x, xa.y);
    const u64 x23 = pk2(xa.z, xa.w);
    const u64 x45 = pk2(xb.x, xb.y);
    const u64 x67 = pk2(xb.z, xb.w);

    // Horner init with highest coefficient w[1000]
    const float wtop = w2s[NCOEF - 1].x;
    u64 y01 = pk2(wtop, wtop);
    u64 y23 = y01, y45 = y01, y67 = y01;

    // 1000 remaining coefficients (999..0) = 500 ulonglong2 elements
    // (element k covers coeffs 2k, 2k+1). Start at k=499; prologue(4) +
    // 124 iters x 4 = 500 exactly.
    const ulonglong2* p = reinterpret_cast<const ulonglong2*>(w2s) + 499;

    ulonglong2 A = p[0];     // {998, 999}
    ulonglong2 B = p[-1];    // {996, 997}
    ulonglong2 C = p[-2];    // {994, 995}
    ulonglong2 D = p[-3];    // {992, 993}
    p -= 4;

#define STEP(wv) \
    y01 = ffma2(y01, x01, (wv)); y23 = ffma2(y23, x23, (wv)); \
    y45 = ffma2(y45, x45, (wv)); y67 = ffma2(y67, x67, (wv));

    #pragma unroll 1
    for (int it = 0; it < 124; ++it) {
        const ulonglong2 A2 = p[0];
        const ulonglong2 B2 = p[-1];
        const ulonglong2 C2 = p[-2];
        const ulonglong2 D2 = p[-3];
        p -= 4;

        STEP(A.y) STEP(A.x)
        STEP(B.y) STEP(B.x)
        STEP(C.y) STEP(C.x)
        STEP(D.y) STEP(D.x)

        A = A2; B = B2; C = C2; D = D2;
    }

    // Peeled final group (coeffs 7..0)
    STEP(A.y) STEP(A.x)
    STEP(B.y) STEP(B.x)
    STEP(C.y) STEP(C.x)
    STEP(D.y) STEP(D.x)
#undef STEP

    float r0, r1, r2, r3, r4, r5, r6, r7;
    asm("mov.b64 {%0, %1}, %2;" : "=f"(r0), "=f"(r1) : "l"(y01));
    asm("mov.b64 {%0, %1}, %2;" : "=f"(r2), "=f"(r3) : "l"(y23));
    asm("mov.b64 {%0, %1}, %2;" : "=f"(r4), "=f"(r5) : "l"(y45));
    asm("mov.b64 {%0, %1}, %2;" : "=f"(r6), "=f"(r7) : "l"(y67));
    float4* o4 = reinterpret_cast<float4*>(out) + 2 * t;
    o4[0] = make_float4(r0, r1, r2, r3);
    o4[1] = make_float4(r4, r5, r6, r7);
}

extern "C" void kernel_launch(void* const* d_in, const int* in_sizes, int n_in,
                              void* d_out, int out_size) {
    const float* x = (const float*)d_in[0];   // (512, 1024) fp32
    const float* w = (const float*)d_in[1];   // (1001,) fp32
    float* out = (float*)d_out;               // (512, 1024) fp32

    const int nthreads = out_size / ELEMS_PER_THREAD;   // 65536
    const int grid = nthreads / THREADS_PER_BLOCK;      // 1024 blocks
    poly_horner_kernel<<<grid, THREADS_PER_BLOCK>>>(x, w, out);
}

// round 5
// speedup vs baseline: 1.1692x; 1.1692x over previous
#include <cuda_runtime.h>

#define NCOEF 1001            // degree 1000 -> 1001 coefficients
#define THREADS_PER_BLOCK 64
#define ELEMS_PER_THREAD 8    // four f32x2 Horner chains per thread

typedef unsigned long long u64;

__device__ __forceinline__ u64 pk2(float a, float b) {
    u64 r;
    asm("mov.b64 %0, {%1, %2};" : "=l"(r) : "f"(a), "f"(b));
    return r;
}
__device__ __forceinline__ u64 ffma2(u64 a, u64 b, u64 c) {
    u64 d;
    asm("fma.rn.f32x2 %0, %1, %2, %3;" : "=l"(d) : "l"(a), "l"(b), "l"(c));
    return d;
}

__global__ __launch_bounds__(THREADS_PER_BLOCK)
void poly_horner_kernel(const float* __restrict__ x,
                        const float* __restrict__ w,
                        float* __restrict__ out) {
    // w duplicated into (w_i, w_i) pairs; hot loop reads ulonglong2
    // (ld.shared.v2.u64 broadcast) -> two ready FFMA2 c-operands per 16B,
    // each amortized over FOUR Horner chains (8 FFMA2 per 16B LDS).
    __shared__ __align__(16) float2 w2s[NCOEF + 1];

    const int t = blockIdx.x * THREADS_PER_BLOCK + threadIdx.x;
    const float4* x4 = reinterpret_cast<const float4*>(x) + 2 * t;
    const float4 xa = x4[0];               // elements 8t .. 8t+3
    const float4 xb = x4[1];               // elements 8t+4 .. 8t+7

    for (int i = threadIdx.x; i < NCOEF; i += THREADS_PER_BLOCK) {
        float v = w[i];
        w2s[i] = make_float2(v, v);
    }
    __syncthreads();

    const u64 x01 = pk2(xa.x, xa.y);
    const u64 x23 = pk2(xa.z, xa.w);
    const u64 x45 = pk2(xb.x, xb.y);
    const u64 x67 = pk2(xb.z, xb.w);

    // Horner init with highest coefficient w[1000]
    const float wtop = w2s[NCOEF - 1].x;
    u64 y01 = pk2(wtop, wtop);
    u64 y23 = y01, y45 = y01, y67 = y01;

    // 1000 remaining coefficients (999..0) = 500 ulonglong2 elements
    // (element k covers coeffs 2k, 2k+1). Start at k=499; prologue(4) +
    // 124 iters x 4 = 500 exactly.
    const ulonglong2* p = reinterpret_cast<const ulonglong2*>(w2s) + 499;

    ulonglong2 A = p[0];     // {998, 999}
    ulonglong2 B = p[-1];    // {996, 997}
    ulonglong2 C = p[-2];    // {994, 995}
    ulonglong2 D = p[-3];    // {992, 993}
    p -= 4;

#define STEP(wv) \
    y01 = ffma2(y01, x01, (wv)); y23 = ffma2(y23, x23, (wv)); \
    y45 = ffma2(y45, x45, (wv)); y67 = ffma2(y67, x67, (wv));

    // unroll 4 (124 = 4*31): the A=A2.. ping-pong copies get register-renamed
    // away across unrolled iterations instead of becoming MOVs (R4 lesson).
    #pragma unroll 4
    for (int it = 0; it < 124; ++it) {
        const ulonglong2 A2 = p[0];
        const ulonglong2 B2 = p[-1];
        const ulonglong2 C2 = p[-2];
        const ulonglong2 D2 = p[-3];
        p -= 4;

        STEP(A.y) STEP(A.x)
        STEP(B.y) STEP(B.x)
        STEP(C.y) STEP(C.x)
        STEP(D.y) STEP(D.x)

        A = A2; B = B2; C = C2; D = D2;
    }

    // Peeled final group (coeffs 7..0)
    STEP(A.y) STEP(A.x)
    STEP(B.y) STEP(B.x)
    STEP(C.y) STEP(C.x)
    STEP(D.y) STEP(D.x)
#undef STEP

    float r0, r1, r2, r3, r4, r5, r6, r7;
    asm("mov.b64 {%0, %1}, %2;" : "=f"(r0), "=f"(r1) : "l"(y01));
    asm("mov.b64 {%0, %1}, %2;" : "=f"(r2), "=f"(r3) : "l"(y23));
    asm("mov.b64 {%0, %1}, %2;" : "=f"(r4), "=f"(r5) : "l"(y45));
    asm("mov.b64 {%0, %1}, %2;" : "=f"(r6), "=f"(r7) : "l"(y67));
    float4* o4 = reinterpret_cast<float4*>(out) + 2 * t;
    o4[0] = make_float4(r0, r1, r2, r3);
    o4[1] = make_float4(r4, r5, r6, r7);
}

extern "C" void kernel_launch(void* const* d_in, const int* in_sizes, int n_in,
                              void* d_out, int out_size) {
    const float* x = (const float*)d_in[0];   // (512, 1024) fp32
    const float* w = (const float*)d_in[1];   // (1001,) fp32
    float* out = (float*)d_out;               // (512, 1024) fp32

    const int nthreads = out_size / ELEMS_PER_THREAD;   // 65536
    const int grid = nthreads / THREADS_PER_BLOCK;      // 1024 blocks
    poly_horner_kernel<<<grid, THREADS_PER_BLOCK>>>(x, w, out);
}

// round 7
// speedup vs baseline: 1.5589x; 1.3333x over previous
#include <cuda_runtime.h>
#include <cuda_bf16.h>
#include <cstdint>

#define THREADS 128
#define NWARP 4
#define TILES_PER_WARP 4
#define NCOEF 1001

__device__ __forceinline__ uint32_t cvta_s(const void* p) {
    return (uint32_t)__cvta_generic_to_shared(p);
}
__device__ __forceinline__ void ldm_x4(uint32_t& r0, uint32_t& r1,
                                       uint32_t& r2, uint32_t& r3, uint32_t addr) {
    asm volatile("ldmatrix.sync.aligned.m8n8.x4.shared.b16 {%0,%1,%2,%3}, [%4];"
                 : "=r"(r0), "=r"(r1), "=r"(r2), "=r"(r3) : "r"(addr));
}
__device__ __forceinline__ void ldm_x2(uint32_t& r0, uint32_t& r1, uint32_t addr) {
    asm volatile("ldmatrix.sync.aligned.m8n8.x2.shared.b16 {%0,%1}, [%2];"
                 : "=r"(r0), "=r"(r1) : "r"(addr));
}
__device__ __forceinline__ void mma16816(float* d, const uint32_t* a,
                                         const uint32_t* b) {
    asm volatile("mma.sync.aligned.m16n8k16.row.col.f32.bf16.bf16.f32 "
                 "{%0,%1,%2,%3}, {%4,%5,%6,%7}, {%8,%9}, {%0,%1,%2,%3};"
                 : "+f"(d[0]), "+f"(d[1]), "+f"(d[2]), "+f"(d[3])
                 : "r"(a[0]), "r"(a[1]), "r"(a[2]), "r"(a[3]),
                   "r"(b[0]), "r"(b[1]));
}

// Layouts: rows are 128B (64 bf16) = 8 chunks of 16B, XOR-swizzled:
//   addr(row, chunk) = base + row*128 + ((chunk ^ (row&7)) & 7)*16
// A tile (per warp): row = element (0..31), chunks 0-3 = p_hi[k0..31],
//   chunks 4-7 = p_lo[k0..31] (bf16 pairs, even power in low half).
// W tile (shared):   row = group n (0..31), chunks 0-3 = w_hi, 4-7 = w_lo.

__global__ __launch_bounds__(THREADS)
void poly_tc_kernel(const float* __restrict__ xg,
                    const float* __restrict__ wg,
                    float* __restrict__ out) {
    __shared__ __align__(128) unsigned char smW[32 * 128];
    __shared__ __align__(128) unsigned char smA[NWARP][32 * 128];

    const int tid  = threadIdx.x;
    const int wid  = tid >> 5;
    const int lane = tid & 31;
    const int g    = lane >> 2;   // 0..7 (mma "groupID")
    const int cL   = lane & 3;    // 0..3 (mma "threadID in group")

    // ---- Build W_hi / W_lo tiles in smem (once per block) ----
    for (int i = tid; i < 1024; i += THREADS) {
        float v = (i < NCOEF) ? wg[i] : 0.0f;
        __nv_bfloat16 hb = __float2bfloat16_rn(v);
        __nv_bfloat16 lb = __float2bfloat16_rn(v - __bfloat162float(hb));
        int n = i >> 5, k = i & 31;
        int ch = k >> 3, byo = (k & 7) * 2;
        *(__nv_bfloat16*)(smW + n * 128 + ((ch ^ (n & 7)) & 7) * 16 + byo) = hb;
        *(__nv_bfloat16*)(smW + n * 128 + (((ch + 4) ^ (n & 7)) & 7) * 16 + byo) = lb;
    }
    __syncthreads();

    // ---- B fragments (K16xN8, col): held in regs for the whole kernel ----
    // bf[part][t][h][r]: part 0=w_hi 1=w_lo, n-tile t (groups 8t..8t+7),
    // k-half h (k 16h..16h+15).
    uint32_t bf[2][4][2][2];
    {
        const uint32_t wbase = cvta_s(smW);
        const int lr = lane & 15;
        #pragma unroll
        for (int part = 0; part < 2; part++)
            #pragma unroll
            for (int t = 0; t < 4; t++)
                #pragma unroll
                for (int h = 0; h < 2; h++) {
                    int row = 8 * t + (lr & 7);
                    int ch  = part * 4 + 2 * h + (lr >> 3);
                    uint32_t addr = wbase + row * 128 + ((ch ^ (row & 7)) & 7) * 16;
                    ldm_x2(bf[part][t][h][0], bf[part][t][h][1], addr);
                }
    }

    const uint32_t abase = cvta_s(smA[wid]);
    const int warp_base = blockIdx.x * (NWARP * TILES_PER_WARP * 32)
                        + wid * (TILES_PER_WARP * 32);

    #pragma unroll 1
    for (int tile = 0; tile < TILES_PER_WARP; tile++) {
        const int tb = warp_base + tile * 32;
        const float x = xg[tb + lane];   // lane <-> element within warp-tile
        float q;

        // ---- powers x^0..x^31, bf16 hi/lo split, store own row ----
        __syncwarp();
        {
            uint32_t hi[16], lo[16];
            float pw = 1.0f;
            #pragma unroll
            for (int i = 0; i < 16; i++) {
                float p0 = pw, p1 = pw * x;
                pw = p1 * x;
                __nv_bfloat162 h2 = __floats2bfloat162_rn(p0, p1); // low=p0
                float r0 = p0 - __low2float(h2);
                float r1 = p1 - __high2float(h2);
                __nv_bfloat162 l2 = __floats2bfloat162_rn(r0, r1);
                hi[i] = *reinterpret_cast<uint32_t*>(&h2);
                lo[i] = *reinterpret_cast<uint32_t*>(&l2);
            }
            q = pw;  // x^32
            #pragma unroll
            for (int c = 0; c < 4; c++) {
                uint32_t ah = abase + lane * 128 + ((c ^ (lane & 7)) & 7) * 16;
                uint32_t al = abase + lane * 128 + (((c + 4) ^ (lane & 7)) & 7) * 16;
                asm volatile("st.shared.v4.b32 [%0], {%1,%2,%3,%4};" :: "r"(ah),
                    "r"(hi[4*c]), "r"(hi[4*c+1]), "r"(hi[4*c+2]), "r"(hi[4*c+3]));
                asm volatile("st.shared.v4.b32 [%0], {%1,%2,%3,%4};" :: "r"(al),
                    "r"(lo[4*c]), "r"(lo[4*c+1]), "r"(lo[4*c+2]), "r"(lo[4*c+3]));
            }
        }
        __syncwarp();

        float yout = 0.0f;
        #pragma unroll
        for (int m = 0; m < 2; m++) {   // M-tile: elements 16m .. 16m+15
            // A fragments: [part][h][4 regs]
            uint32_t A[2][2][4];
            #pragma unroll
            for (int part = 0; part < 2; part++)
                #pragma unroll
                for (int h = 0; h < 2; h++) {
                    int row = 16 * m + (lane & 15);
                    int ch  = part * 4 + 2 * h + (lane >> 4);
                    uint32_t addr = abase + row * 128 + ((ch ^ (row & 7)) & 7) * 16;
                    ldm_x4(A[part][h][0], A[part][h][1],
                           A[part][h][2], A[part][h][3], addr);
                }

            // D[t][r]: 16x8 fp32 per n-tile; 3-term split = 6 mma per tile
            float D[4][4];
            #pragma unroll
            for (int t = 0; t < 4; t++) {
                D[t][0] = D[t][1] = D[t][2] = D[t][3] = 0.0f;
                mma16816(D[t], A[0][0], bf[0][t][0]);  // p_hi k0-15  x w_hi
                mma16816(D[t], A[0][1], bf[0][t][1]);  // p_hi k16-31 x w_hi
                mma16816(D[t], A[1][0], bf[0][t][0]);  // p_lo k0-15  x w_hi
                mma16816(D[t], A[1][1], bf[0][t][1]);  // p_lo k16-31 x w_hi
                mma16816(D[t], A[0][0], bf[1][t][0]);  // p_hi k0-15  x w_lo
                mma16816(D[t], A[0][1], bf[1][t][1]);  // p_hi k16-31 x w_lo
            }

            // ---- epilogue: y_e = sum_j S_j q^j via quad-split Horner ----
            // thread holds S_j for j = 8t + 2cL (+1); rows g (b=0), g+8 (b=1)
            float qe0 = __shfl_sync(0xffffffffu, q, 16 * m + g);
            float qe1 = __shfl_sync(0xffffffffu, q, 16 * m + g + 8);
            #pragma unroll
            for (int b = 0; b < 2; b++) {
                float qe  = b ? qe1 : qe0;
                float s0p = fmaf(qe, D[0][2*b+1], D[0][2*b]);
                float s1p = fmaf(qe, D[1][2*b+1], D[1][2*b]);
                float s2p = fmaf(qe, D[2][2*b+1], D[2][2*b]);
                float s3p = fmaf(qe, D[3][2*b+1], D[3][2*b]);
                float qe2 = qe * qe, qe4 = qe2 * qe2;
                float qe6 = qe4 * qe2, qe8 = qe4 * qe4;
                float P = fmaf(fmaf(fmaf(s3p, qe8, s2p), qe8, s1p), qe8, s0p);
                float qp = (cL == 0) ? 1.0f : (cL == 1) ? qe2
                         : (cL == 2) ? qe4 : qe6;
                float v = P * qp;
                v += __shfl_xor_sync(0xffffffffu, v, 1);
                v += __shfl_xor_sync(0xffffffffu, v, 2);
                if (((cL >> 1) == m) && ((cL & 1) == b)) yout = v;
            }
        }
        // lane (4g + cL) writes element 16*(cL>>1) + g + 8*(cL&1): all 32 unique
        out[tb + 16 * (cL >> 1) + g + 8 * (cL & 1)] = yout;
    }
}

extern "C" void kernel_launch(void* const* d_in, const int* in_sizes, int n_in,
                              void* d_out, int out_size) {
    const float* x = (const float*)d_in[0];   // (512, 1024) fp32
    const float* w = (const float*)d_in[1];   // (1001,) fp32
    float* out = (float*)d_out;

    const int grid = out_size / (NWARP * TILES_PER_WARP * 32);   // 1024
    poly_tc_kernel<<<grid, THREADS>>>(x, w, out);
}

// round 8
// speedup vs baseline: 1.6439x; 1.0545x over previous
#include <cuda_runtime.h>
#include <cuda_bf16.h>
#include <cstdint>

#define THREADS 128
#define NWARP 4
#define TILES_PER_WARP 2
#define NCOEF 1001

__device__ __forceinline__ uint32_t cvta_s(const void* p) {
    return (uint32_t)__cvta_generic_to_shared(p);
}
__device__ __forceinline__ void ldm_x4(uint32_t& r0, uint32_t& r1,
                                       uint32_t& r2, uint32_t& r3, uint32_t addr) {
    asm volatile("ldmatrix.sync.aligned.m8n8.x4.shared.b16 {%0,%1,%2,%3}, [%4];"
                 : "=r"(r0), "=r"(r1), "=r"(r2), "=r"(r3) : "r"(addr));
}
__device__ __forceinline__ void ldm_x2(uint32_t& r0, uint32_t& r1, uint32_t addr) {
    asm volatile("ldmatrix.sync.aligned.m8n8.x2.shared.b16 {%0,%1}, [%2];"
                 : "=r"(r0), "=r"(r1) : "r"(addr));
}
__device__ __forceinline__ void mma16816(float* d, const uint32_t* a,
                                         const uint32_t* b) {
    asm volatile("mma.sync.aligned.m16n8k16.row.col.f32.bf16.bf16.f32 "
                 "{%0,%1,%2,%3}, {%4,%5,%6,%7}, {%8,%9}, {%0,%1,%2,%3};"
                 : "+f"(d[0]), "+f"(d[1]), "+f"(d[2]), "+f"(d[3])
                 : "r"(a[0]), "r"(a[1]), "r"(a[2]), "r"(a[3]),
                   "r"(b[0]), "r"(b[1]));
}

// Layouts: rows are 128B (64 bf16) = 8 chunks of 16B, XOR-swizzled:
//   addr(row, chunk) = base + row*128 + ((chunk ^ (row&7)) & 7)*16
// A tile (per warp): row = element (0..31), chunks 0-3 = p_hi[k0..31],
//   chunks 4-7 = p_lo[k0..31] (bf16 pairs, even power in low half).
// W tile (shared):   row = group n (0..31), chunks 0-3 = w_hi, 4-7 = w_lo.

__global__ __launch_bounds__(THREADS)
void poly_tc_kernel(const float* __restrict__ xg,
                    const float* __restrict__ wg,
                    float* __restrict__ out) {
    __shared__ __align__(128) unsigned char smW[32 * 128];
    __shared__ __align__(128) unsigned char smA[NWARP][32 * 128];

    const int tid  = threadIdx.x;
    const int wid  = tid >> 5;
    const int lane = tid & 31;
    const int g    = lane >> 2;   // 0..7 (mma "groupID")
    const int cL   = lane & 3;    // 0..3 (mma "threadID in group")

    const int warp_base = blockIdx.x * (NWARP * TILES_PER_WARP * 32)
                        + wid * (TILES_PER_WARP * 32);
    // Prefetch x for tile 0 before the W-build / syncthreads.
    float x_next = xg[warp_base + lane];

    // ---- Build W_hi / W_lo tiles in smem (once per block) ----
    for (int i = tid; i < 1024; i += THREADS) {
        float v = (i < NCOEF) ? wg[i] : 0.0f;
        __nv_bfloat16 hb = __float2bfloat16_rn(v);
        __nv_bfloat16 lb = __float2bfloat16_rn(v - __bfloat162float(hb));
        int n = i >> 5, k = i & 31;
        int ch = k >> 3, byo = (k & 7) * 2;
        *(__nv_bfloat16*)(smW + n * 128 + ((ch ^ (n & 7)) & 7) * 16 + byo) = hb;
        *(__nv_bfloat16*)(smW + n * 128 + (((ch + 4) ^ (n & 7)) & 7) * 16 + byo) = lb;
    }
    __syncthreads();

    // ---- B fragments (K16xN8, col): held in regs for the whole kernel ----
    // bf[part][t][h][r]: part 0=w_hi 1=w_lo, n-tile t (groups 8t..8t+7),
    // k-half h (k 16h..16h+15).
    uint32_t bf[2][4][2][2];
    {
        const uint32_t wbase = cvta_s(smW);
        const int lr = lane & 15;
        #pragma unroll
        for (int part = 0; part < 2; part++)
            #pragma unroll
            for (int t = 0; t < 4; t++)
                #pragma unroll
                for (int h = 0; h < 2; h++) {
                    int row = 8 * t + (lr & 7);
                    int ch  = part * 4 + 2 * h + (lr >> 3);
                    uint32_t addr = wbase + row * 128 + ((ch ^ (row & 7)) & 7) * 16;
                    ldm_x2(bf[part][t][h][0], bf[part][t][h][1], addr);
                }
    }

    const uint32_t abase = cvta_s(smA[wid]);

    #pragma unroll 1
    for (int tile = 0; tile < TILES_PER_WARP; tile++) {
        const int tb = warp_base + tile * 32;
        const float x = x_next;
        if (tile + 1 < TILES_PER_WARP)
            x_next = xg[tb + 32 + lane];   // overlap LDG with this tile's work
        float q;

        // ---- powers x^0..x^31, bf16 hi/lo split, store own row ----
        __syncwarp();
        {
            uint32_t hi[16], lo[16];
            float pw = 1.0f;
            #pragma unroll
            for (int i = 0; i < 16; i++) {
                float p0 = pw, p1 = pw * x;
                pw = p1 * x;
                __nv_bfloat162 h2 = __floats2bfloat162_rn(p0, p1); // low=p0
                float r0 = p0 - __low2float(h2);
                float r1 = p1 - __high2float(h2);
                __nv_bfloat162 l2 = __floats2bfloat162_rn(r0, r1);
                hi[i] = *reinterpret_cast<uint32_t*>(&h2);
                lo[i] = *reinterpret_cast<uint32_t*>(&l2);
            }
            q = pw;  // x^32
            #pragma unroll
            for (int c = 0; c < 4; c++) {
                uint32_t ah = abase + lane * 128 + ((c ^ (lane & 7)) & 7) * 16;
                uint32_t al = abase + lane * 128 + (((c + 4) ^ (lane & 7)) & 7) * 16;
                asm volatile("st.shared.v4.b32 [%0], {%1,%2,%3,%4};" :: "r"(ah),
                    "r"(hi[4*c]), "r"(hi[4*c+1]), "r"(hi[4*c+2]), "r"(hi[4*c+3]));
                asm volatile("st.shared.v4.b32 [%0], {%1,%2,%3,%4};" :: "r"(al),
                    "r"(lo[4*c]), "r"(lo[4*c+1]), "r"(lo[4*c+2]), "r"(lo[4*c+3]));
            }
        }
        __syncwarp();

        float yout = 0.0f;
        #pragma unroll
        for (int m = 0; m < 2; m++) {   // M-tile: elements 16m .. 16m+15
            // A fragments: [part][h][4 regs]
            uint32_t A[2][2][4];
            #pragma unroll
            for (int part = 0; part < 2; part++)
                #pragma unroll
                for (int h = 0; h < 2; h++) {
                    int row = 16 * m + (lane & 15);
                    int ch  = part * 4 + 2 * h + (lane >> 4);
                    uint32_t addr = abase + row * 128 + ((ch ^ (row & 7)) & 7) * 16;
                    ldm_x4(A[part][h][0], A[part][h][1],
                           A[part][h][2], A[part][h][3], addr);
                }

            // D[t][r]: 16x8 fp32 per n-tile; 3-term split = 6 mma per tile
            float D[4][4];
            #pragma unroll
            for (int t = 0; t < 4; t++) {
                D[t][0] = D[t][1] = D[t][2] = D[t][3] = 0.0f;
                mma16816(D[t], A[0][0], bf[0][t][0]);  // p_hi k0-15  x w_hi
                mma16816(D[t], A[0][1], bf[0][t][1]);  // p_hi k16-31 x w_hi
                mma16816(D[t], A[1][0], bf[0][t][0]);  // p_lo k0-15  x w_hi
                mma16816(D[t], A[1][1], bf[0][t][1]);  // p_lo k16-31 x w_hi
                mma16816(D[t], A[0][0], bf[1][t][0]);  // p_hi k0-15  x w_lo
                mma16816(D[t], A[0][1], bf[1][t][1]);  // p_hi k16-31 x w_lo
            }

            // ---- epilogue: y_e = sum_j S_j q^j via quad-split Horner ----
            // thread holds S_j for j = 8t + 2cL (+1); rows g (b=0), g+8 (b=1)
            float qe0 = __shfl_sync(0xffffffffu, q, 16 * m + g);
            float qe1 = __shfl_sync(0xffffffffu, q, 16 * m + g + 8);
            #pragma unroll
            for (int b = 0; b < 2; b++) {
                float qe  = b ? qe1 : qe0;
                float s0p = fmaf(qe, D[0][2*b+1], D[0][2*b]);
                float s1p = fmaf(qe, D[1][2*b+1], D[1][2*b]);
                float s2p = fmaf(qe, D[2][2*b+1], D[2][2*b]);
                float s3p = fmaf(qe, D[3][2*b+1], D[3][2*b]);
                float qe2 = qe * qe, qe4 = qe2 * qe2;
                float qe6 = qe4 * qe2, qe8 = qe4 * qe4;
                float P = fmaf(fmaf(fmaf(s3p, qe8, s2p), qe8, s1p), qe8, s0p);
                float qp = (cL == 0) ? 1.0f : (cL == 1) ? qe2
                         : (cL == 2) ? qe4 : qe6;
                float v = P * qp;
                v += __shfl_xor_sync(0xffffffffu, v, 1);
                v += __shfl_xor_sync(0xffffffffu, v, 2);
                if (((cL >> 1) == m) && ((cL & 1) == b)) yout = v;
            }
        }
        // lane (4g + cL) writes element 16*(cL>>1) + g + 8*(cL&1): all 32 unique
        out[tb + 16 * (cL >> 1) + g + 8 * (cL & 1)] = yout;
    }
}

extern "C" void kernel_launch(void* const* d_in, const int* in_sizes, int n_in,
                              void* d_out, int out_size) {
    const float* x = (const float*)d_in[0];   // (512, 1024) fp32
    const float* w = (const float*)d_in[1];   // (1001,) fp32
    float* out = (float*)d_out;

    const int grid = out_size / (NWARP * TILES_PER_WARP * 32);   // 2048
    poly_tc_kernel<<<grid, THREADS>>>(x, w, out);
}